// round 13
// baseline (speedup 1.0000x reference)
#include <cuda_runtime.h>
#include <cuda_fp16.h>
#include <math.h>
#include <stdint.h>

#define N_CELLS 16384
#define H 512
#define D 512
#define KNB 15
#define EM_STRIDE 32          // one fp32 accumulator per 128B line

// ---------------- scratch ----------------
__device__ __align__(16) __half2 g_v  [N_CELLS * H];   // v = sqrt(|s|)*unit(s)
__device__ __align__(16) __half2 g_new[N_CELLS * H];
__device__ int    g_lasing[N_CELLS];
__device__ int    g_las_list[N_CELLS];
__device__ int    g_nlasing;
__device__ float  g_em_re_s[H * EM_STRIDE];   // strided accumulators (line-spread)
__device__ float  g_em_im_s[H * EM_STRIDE];
__device__ float  g_cavn_re[H];
__device__ float  g_cavn_im[H];
__device__ float  g_cav_phase[H];
__device__ double g_sum, g_sum2;
__device__ unsigned int g_done;

// ---------------- K1: pump -> lasing mask + compaction ----------------
__global__ void k_pump(const float* __restrict__ x,
                       const float* __restrict__ W,
                       const float* __restrict__ b,
                       const float* __restrict__ excited) {
    int warp = threadIdx.x >> 5;
    int lane = threadIdx.x & 31;
    int cell = blockIdx.x * 8 + warp;
    const float* w = W + (size_t)cell * D;
    float s = 0.f;
#pragma unroll
    for (int t = 0; t < D / 32; t++)
        s += x[lane + 32 * t] * w[lane + 32 * t];
#pragma unroll
    for (int o = 16; o; o >>= 1) s += __shfl_xor_sync(0xFFFFFFFFu, s, o);

    __shared__ int sflag[8];
    __shared__ int sbase;
    if (lane == 0) {
        float z = s + b[cell];
        float pump = 1.f / (1.f + expf(-z));
        float e = excited[cell] * 0.95f + pump * 0.05f;
        e = fminf(fmaxf(e, 0.f), 1.f);
        int las = (e > 0.5f) ? 1 : 0;
        g_lasing[cell] = las;
        sflag[warp] = las;
    }
    __syncthreads();
    if (threadIdx.x < 8) {
        unsigned m = __ballot_sync(0x000000FFu, sflag[threadIdx.x]);
        int total = __popc(m);
        if (threadIdx.x == 0 && total) sbase = atomicAdd(&g_nlasing, total);
        __syncwarp(0x000000FFu);
        if (sflag[threadIdx.x]) {
            int pos = sbase + __popc(m & ((1u << threadIdx.x) - 1u));
            g_las_list[pos] = blockIdx.x * 8 + threadIdx.x;
        }
    }
}

// ---------------- K2: rotate (Taylor) + scale to v = s/sqrt(|s|) ----------------
__global__ void k_rot(const float4* __restrict__ cr,
                      const float4* __restrict__ ci,
                      const float4* __restrict__ pv) {
    int i = blockIdx.x * blockDim.x + threadIdx.x;   // over N*H/4
    if (blockIdx.x == 0) {
        float4 z4 = make_float4(0.f, 0.f, 0.f, 0.f);
        for (int j = threadIdx.x; j < H * EM_STRIDE / 4; j += blockDim.x) {
            ((float4*)g_em_re_s)[j] = z4;
            ((float4*)g_em_im_s)[j] = z4;
        }
        if (threadIdx.x == 0) {
            g_nlasing = 0; g_sum = 0.0; g_sum2 = 0.0; g_done = 0u;
        }
    }
    if (i >= (N_CELLS * H) / 4) return;
    float4 a4 = cr[i], b4 = ci[i], p4 = pv[i];
    float ax[4] = {a4.x, a4.y, a4.z, a4.w};
    float bx[4] = {b4.x, b4.y, b4.z, b4.w};
    float px[4] = {p4.x, p4.y, p4.z, p4.w};
    uint4 outp;
    unsigned int* op = (unsigned int*)&outp;
#pragma unroll
    for (int q = 0; q < 4; q++) {
        float ang = 0.1f * px[q];
        float a2 = ang * ang;
        float cs = 1.f - 0.5f * a2;
        float sn = ang * (1.f - a2 * (1.f / 6.f));
        float re = ax[q] * cs - bx[q] * sn;
        float im = ax[q] * sn + bx[q] * cs;
        float m2 = fmaxf(re * re + im * im, 1e-30f);
        float qm = rsqrtf(sqrtf(m2));               // |s|^(-1/2)
        __half2 h = __floats2half2_rn(re * qm, im * qm);
        op[q] = *(unsigned int*)&h;
    }
    *(uint4*)((unsigned int*)g_v + (size_t)i * 4) = outp;
}

// ---------------- K3: neighbor coupling (Gram-matrix, half2 SIMD) ----------
__global__ void __launch_bounds__(128) k_couple(const int* __restrict__ nbr) {
    int cell = blockIdx.x;
    int t = threadIdx.x;
    __shared__ int snb[16];
    if (t < KNB) snb[t] = nbr[cell * KNB + t];
    __syncthreads();

    int chbase = t * 4;
    const __half2 z2 = __floats2half2_rn(0.f, 0.f);
    __half2 sq0 = z2, sq1 = z2, sq2 = z2, sq3 = z2;
    __half2 xy01 = z2, xy23 = z2;

#pragma unroll 3
    for (int j = 0; j < KNB; j++) {
        const uint4 np = *(const uint4*)(g_v + (size_t)snb[j] * H + chbase);
        __half2 n0 = *(const __half2*)&np.x;
        __half2 n1 = *(const __half2*)&np.y;
        __half2 n2 = *(const __half2*)&np.z;
        __half2 n3 = *(const __half2*)&np.w;
        sq0 = __hfma2(n0, n0, sq0);
        sq1 = __hfma2(n1, n1, sq1);
        sq2 = __hfma2(n2, n2, sq2);
        sq3 = __hfma2(n3, n3, sq3);
        unsigned int p, q;
        p = __byte_perm(np.x, np.y, 0x5410);
        q = __byte_perm(np.x, np.y, 0x7632);
        xy01 = __hfma2(*(__half2*)&p, *(__half2*)&q, xy01);
        p = __byte_perm(np.z, np.w, 0x5410);
        q = __byte_perm(np.z, np.w, 0x7632);
        xy23 = __hfma2(*(__half2*)&p, *(__half2*)&q, xy23);
    }

    size_t base = (size_t)cell * H + chbase;
    uint4 vp = *(const uint4*)(g_v + base);
    float2 v[4];
    v[0] = __half22float2(*(const __half2*)&vp.x);
    v[1] = __half22float2(*(const __half2*)&vp.y);
    v[2] = __half22float2(*(const __half2*)&vp.z);
    v[3] = __half22float2(*(const __half2*)&vp.w);

    float2 sqf[4];
    sqf[0] = __half22float2(sq0); sqf[1] = __half22float2(sq1);
    sqf[2] = __half22float2(sq2); sqf[3] = __half22float2(sq3);
    float2 xya = __half22float2(xy01);
    float2 xyb = __half22float2(xy23);
    float sxy[4] = {xya.x, xya.y, xyb.x, xyb.y};

    const float CF = 0.3f * 0.1f / (float)KNB;  // 0.002
    uint4 outp;
    unsigned int* op = (unsigned int*)&outp;
#pragma unroll
    for (int qc = 0; qc < 4; qc++) {
        float vx = v[qc].x, vy = v[qc].y;
        float ir = vx * sqf[qc].x + vy * sxy[qc];
        float ii = vx * sxy[qc]   + vy * sqf[qc].y;
        float a2 = fmaxf(vx * vx + vy * vy, 1e-30f);
        float inv = rsqrtf(a2);
        float amp = a2 * inv;
        __half2 h = __floats2half2_rn(0.7f * amp * vx + CF * inv * ir,
                                      0.7f * amp * vy + CF * inv * ii);
        op[qc] = *(unsigned int*)&h;
    }
    *(uint4*)(g_new + base) = outp;
}

// ---------------- K4: emission — chunk per block, batch-8, line-spread atomics
__global__ void __launch_bounds__(128) k_emit() {
    int t = threadIdx.x;
    int nl = g_nlasing;
    int chunk = (nl + gridDim.x - 1) / gridDim.x;
    int i0 = blockIdx.x * chunk;
    int i1 = min(i0 + chunk, nl);
    if (i0 >= i1) return;

    size_t toff = (size_t)t * 4;
    float sr0 = 0, sr1 = 0, sr2 = 0, sr3 = 0, si0 = 0, si1 = 0, si2 = 0, si3 = 0;

    for (int i = i0; i < i1; i += 8) {
        int m = i1 - i;
        int ids[8];
#pragma unroll
        for (int u = 0; u < 8; u++)
            ids[u] = (u < m) ? g_las_list[i + u] : -1;    // broadcast loads
        uint4 p[8];
#pragma unroll
        for (int u = 0; u < 8; u++)
            p[u] = (ids[u] >= 0) ? *(const uint4*)(g_new + (size_t)ids[u] * H + toff)
                                 : make_uint4(0, 0, 0, 0);
#pragma unroll
        for (int u = 0; u < 8; u++) {
            float2 a = __half22float2(*(const __half2*)&p[u].x);
            float2 b = __half22float2(*(const __half2*)&p[u].y);
            float2 c = __half22float2(*(const __half2*)&p[u].z);
            float2 d = __half22float2(*(const __half2*)&p[u].w);
            sr0 += a.x; si0 += a.y;
            sr1 += b.x; si1 += b.y;
            sr2 += c.x; si2 += c.y;
            sr3 += d.x; si3 += d.y;
        }
    }
    int h = t * 4;
    atomicAdd(&g_em_re_s[(h + 0) * EM_STRIDE], sr0);
    atomicAdd(&g_em_re_s[(h + 1) * EM_STRIDE], sr1);
    atomicAdd(&g_em_re_s[(h + 2) * EM_STRIDE], sr2);
    atomicAdd(&g_em_re_s[(h + 3) * EM_STRIDE], sr3);
    atomicAdd(&g_em_im_s[(h + 0) * EM_STRIDE], si0);
    atomicAdd(&g_em_im_s[(h + 1) * EM_STRIDE], si1);
    atomicAdd(&g_em_im_s[(h + 2) * EM_STRIDE], si2);
    atomicAdd(&g_em_im_s[(h + 3) * EM_STRIDE], si3);
}

// ---------------- K5a: cavity update ----------------
__global__ void __launch_bounds__(512) k_cav_update(const float* __restrict__ cav_re,
                                                    const float* __restrict__ cav_im) {
    int t = threadIdx.x;
    int nl = g_nlasing;
    float inv = 1.f / fmaxf((float)nl, 1.f);
    float cr = cav_re[t], ci = cav_im[t];
    float er = g_em_re_s[t * EM_STRIDE];
    float ei = g_em_im_s[t * EM_STRIDE];
    float nr = (nl > 0) ? 0.8f * cr + 0.2f * (er * inv) : cr;
    float ni = (nl > 0) ? 0.8f * ci + 0.2f * (ei * inv) : ci;
    g_cavn_re[t] = nr;
    g_cavn_im[t] = ni;
    g_cav_phase[t] = atan2f(ci, cr);   // OLD cavity phase
}

// ---------------- K5b: decode GEMV ----------------
__global__ void __launch_bounds__(128) k_decode(const float* __restrict__ decW,
                                                const float* __restrict__ decb,
                                                float* __restrict__ out) {
    int d = blockIdx.x;
    int t = threadIdx.x;
    const float* w = decW + (size_t)d * (2 * H);
    float s = 0.f;
#pragma unroll
    for (int j = t; j < 2 * H; j += 128) {
        float v = (j < H) ? g_cavn_re[j] : g_cavn_im[j - H];
        s = fmaf(v, w[j], s);
    }
#pragma unroll
    for (int o = 16; o; o >>= 1) s += __shfl_xor_sync(0xFFFFFFFFu, s, o);
    __shared__ float red[4];
    if ((t & 31) == 0) red[t >> 5] = s;
    __syncthreads();
    if (t == 0) out[d] = red[0] + red[1] + red[2] + red[3] + decb[d];
}

// ---------------- K6: finalize + variance + fused tension ----------------
__global__ void __launch_bounds__(128) k_final(float* __restrict__ out, int out_size) {
    int cell = blockIdx.x;
    int t = threadIdx.x;
    int wid = t >> 5, lane = t & 31;
    __shared__ float wmax[4];
    __shared__ float ws[4], ws2[4];

    size_t base = (size_t)cell * H + (size_t)t * 4;
    uint4 p = *(const uint4*)(g_new + base);
    float2 c0 = __half22float2(*(const __half2*)&p.x);
    float2 c1 = __half22float2(*(const __half2*)&p.y);
    float2 c2 = __half22float2(*(const __half2*)&p.z);
    float2 c3 = __half22float2(*(const __half2*)&p.w);
    int las = g_lasing[cell];

    float amp[4];
    float re_[4] = {c0.x, c1.x, c2.x, c3.x};
    float im_[4] = {c0.y, c1.y, c2.y, c3.y};
    float mx = 0.f;
#pragma unroll
    for (int q = 0; q < 4; q++) {
        int h = t * 4 + q;
        float re = re_[q], im = im_[q];
        if (las) {
            float a = sqrtf(re * re + im * im);
            float ang = 0.3f * g_cav_phase[h] + 0.7f * atan2f(im, re);
            float sn, cs;
            __sincosf(ang, &sn, &cs);
            re = a * cs;
            im = a * sn;
        }
        re += 0.05f * g_cavn_re[h];
        im += 0.05f * g_cavn_im[h];
        amp[q] = sqrtf(re * re + im * im);
        mx = fmaxf(mx, amp[q]);
    }
#pragma unroll
    for (int o = 16; o; o >>= 1) mx = fmaxf(mx, __shfl_xor_sync(0xFFFFFFFFu, mx, o));
    if (lane == 0) wmax[wid] = mx;
    __syncthreads();
    float bmax = fmaxf(fmaxf(wmax[0], wmax[1]), fmaxf(wmax[2], wmax[3]));
    float inv = 1.f / (bmax + 1e-8f);

    float s = 0.f, s2 = 0.f;
#pragma unroll
    for (int q = 0; q < 4; q++) {
        float an = amp[q] * inv;
        s += an;
        s2 = fmaf(an, an, s2);
    }
#pragma unroll
    for (int o = 16; o; o >>= 1) {
        s  += __shfl_xor_sync(0xFFFFFFFFu, s, o);
        s2 += __shfl_xor_sync(0xFFFFFFFFu, s2, o);
    }
    if (lane == 0) { ws[wid] = s; ws2[wid] = s2; }
    __syncthreads();
    if (t == 0) {
        float bs  = ws[0] + ws[1] + ws[2] + ws[3];
        float bs2 = ws2[0] + ws2[1] + ws2[2] + ws2[3];
        atomicAdd(&g_sum,  (double)bs);
        atomicAdd(&g_sum2, (double)bs2);
        __threadfence();
        unsigned int done = atomicAdd(&g_done, 1u);
        if (done == gridDim.x - 1) {
            double S  = atomicAdd(&g_sum,  0.0);
            double S2 = atomicAdd(&g_sum2, 0.0);
            double M = (double)N_CELLS * (double)H;
            double mean = S / M;
            double var = S2 / M - mean * mean;
            out[out_size - 1] = (float)var;
        }
    }
}

// ---------------- launcher ----------------
extern "C" void kernel_launch(void* const* d_in, const int* in_sizes, int n_in,
                              void* d_out, int out_size) {
    const float* x       = (const float*)d_in[0];
    const float* pump_W  = (const float*)d_in[1];
    const float* pump_b  = (const float*)d_in[2];
    const float* dec_W   = (const float*)d_in[3];
    const float* dec_b   = (const float*)d_in[4];
    const float* cs_re   = (const float*)d_in[5];
    const float* cs_im   = (const float*)d_in[6];
    const float* excited = (const float*)d_in[7];
    const float* phase_v = (const float*)d_in[8];
    const float* cav_re  = (const float*)d_in[9];
    const float* cav_im  = (const float*)d_in[10];
    const int*   nbr     = (const int*)d_in[11];
    float* out = (float*)d_out;

    k_rot<<<(N_CELLS * H / 4) / 256, 256>>>((const float4*)cs_re,
                                            (const float4*)cs_im,
                                            (const float4*)phase_v);
    k_pump<<<N_CELLS / 8, 256>>>(x, pump_W, pump_b, excited);
    k_couple<<<N_CELLS, 128>>>(nbr);
    k_emit<<<128, 128>>>();
    k_cav_update<<<1, 512>>>(cav_re, cav_im);
    k_decode<<<D, 128>>>(dec_W, dec_b, out);
    k_final<<<N_CELLS, 128>>>(out, out_size);
}

// round 14
// speedup vs baseline: 1.2293x; 1.2293x over previous
#include <cuda_runtime.h>
#include <cuda_fp16.h>
#include <math.h>
#include <stdint.h>

#define N_CELLS 16384
#define H 512
#define D 512
#define KNB 15
#define EM_STRIDE 32          // one fp32 accumulator per 128B line

// ---------------- scratch ----------------
__device__ __align__(16) __half2 g_v  [N_CELLS * H];   // v = sqrt(|s|)*unit(s)
__device__ __align__(16) __half2 g_new[N_CELLS * H];
__device__ int    g_lasing[N_CELLS];
__device__ int    g_nlasing;
__device__ float  g_em_re_s[H * EM_STRIDE];   // line-spread accumulators
__device__ float  g_em_im_s[H * EM_STRIDE];
__device__ float  g_cavn_re[H];
__device__ float  g_cavn_im[H];
__device__ float  g_cav_phase[H];
__device__ double g_sum, g_sum2;
__device__ unsigned int g_done;

// ---------------- K1: pump -> lasing mask + count ----------------
__global__ void k_pump(const float* __restrict__ x,
                       const float* __restrict__ W,
                       const float* __restrict__ b,
                       const float* __restrict__ excited) {
    int warp = threadIdx.x >> 5;
    int lane = threadIdx.x & 31;
    int cell = blockIdx.x * 8 + warp;
    const float* w = W + (size_t)cell * D;
    float s = 0.f;
#pragma unroll
    for (int t = 0; t < D / 32; t++)
        s += x[lane + 32 * t] * w[lane + 32 * t];
#pragma unroll
    for (int o = 16; o; o >>= 1) s += __shfl_xor_sync(0xFFFFFFFFu, s, o);

    __shared__ int sflag[8];
    if (lane == 0) {
        float z = s + b[cell];
        float pump = 1.f / (1.f + expf(-z));
        float e = excited[cell] * 0.95f + pump * 0.05f;
        e = fminf(fmaxf(e, 0.f), 1.f);
        int las = (e > 0.5f) ? 1 : 0;
        g_lasing[cell] = las;
        sflag[warp] = las;
    }
    __syncthreads();
    if (threadIdx.x < 8) {
        unsigned m = __ballot_sync(0x000000FFu, sflag[threadIdx.x]);
        if (threadIdx.x == 0 && m) atomicAdd(&g_nlasing, __popc(m));
    }
}

// ---------------- K2: rotate (Taylor) + scale to v = s/sqrt(|s|) ----------------
// block 0 zeroes the emission accumulators + scalars (stream order guards couple)
__global__ void k_rot(const float4* __restrict__ cr,
                      const float4* __restrict__ ci,
                      const float4* __restrict__ pv) {
    int i = blockIdx.x * blockDim.x + threadIdx.x;   // over N*H/4
    if (blockIdx.x == 0) {
        float4 z4 = make_float4(0.f, 0.f, 0.f, 0.f);
        for (int j = threadIdx.x; j < H * EM_STRIDE / 4; j += blockDim.x) {
            ((float4*)g_em_re_s)[j] = z4;
            ((float4*)g_em_im_s)[j] = z4;
        }
        if (threadIdx.x == 0) {
            g_nlasing = 0; g_sum = 0.0; g_sum2 = 0.0; g_done = 0u;
        }
    }
    if (i >= (N_CELLS * H) / 4) return;
    float4 a4 = cr[i], b4 = ci[i], p4 = pv[i];
    float ax[4] = {a4.x, a4.y, a4.z, a4.w};
    float bx[4] = {b4.x, b4.y, b4.z, b4.w};
    float px[4] = {p4.x, p4.y, p4.z, p4.w};
    uint4 outp;
    unsigned int* op = (unsigned int*)&outp;
#pragma unroll
    for (int q = 0; q < 4; q++) {
        float ang = 0.1f * px[q];
        float a2 = ang * ang;
        float cs = 1.f - 0.5f * a2;
        float sn = ang * (1.f - a2 * (1.f / 6.f));
        float re = ax[q] * cs - bx[q] * sn;
        float im = ax[q] * sn + bx[q] * cs;
        float m2 = fmaxf(re * re + im * im, 1e-30f);
        float qm = rsqrtf(sqrtf(m2));               // |s|^(-1/2)
        __half2 h = __floats2half2_rn(re * qm, im * qm);
        op[q] = *(unsigned int*)&h;
    }
    *(uint4*)((unsigned int*)g_v + (size_t)i * 4) = outp;
}

// ---------------- K3: coupling (Gram) + fused line-spread emission ----------
__global__ void __launch_bounds__(128) k_couple(const int* __restrict__ nbr) {
    int cell = blockIdx.x;
    int t = threadIdx.x;
    __shared__ int snb[16];
    if (t < KNB) snb[t] = nbr[cell * KNB + t];
    __syncthreads();

    int chbase = t * 4;
    const __half2 z2 = __floats2half2_rn(0.f, 0.f);
    __half2 sq0 = z2, sq1 = z2, sq2 = z2, sq3 = z2;
    __half2 xy01 = z2, xy23 = z2;

#pragma unroll 3
    for (int j = 0; j < KNB; j++) {
        const uint4 np = *(const uint4*)(g_v + (size_t)snb[j] * H + chbase);
        __half2 n0 = *(const __half2*)&np.x;
        __half2 n1 = *(const __half2*)&np.y;
        __half2 n2 = *(const __half2*)&np.z;
        __half2 n3 = *(const __half2*)&np.w;
        sq0 = __hfma2(n0, n0, sq0);
        sq1 = __hfma2(n1, n1, sq1);
        sq2 = __hfma2(n2, n2, sq2);
        sq3 = __hfma2(n3, n3, sq3);
        unsigned int p, q;
        p = __byte_perm(np.x, np.y, 0x5410);
        q = __byte_perm(np.x, np.y, 0x7632);
        xy01 = __hfma2(*(__half2*)&p, *(__half2*)&q, xy01);
        p = __byte_perm(np.z, np.w, 0x5410);
        q = __byte_perm(np.z, np.w, 0x7632);
        xy23 = __hfma2(*(__half2*)&p, *(__half2*)&q, xy23);
    }

    size_t base = (size_t)cell * H + chbase;
    uint4 vp = *(const uint4*)(g_v + base);
    float2 v[4];
    v[0] = __half22float2(*(const __half2*)&vp.x);
    v[1] = __half22float2(*(const __half2*)&vp.y);
    v[2] = __half22float2(*(const __half2*)&vp.z);
    v[3] = __half22float2(*(const __half2*)&vp.w);

    float2 sqf[4];
    sqf[0] = __half22float2(sq0); sqf[1] = __half22float2(sq1);
    sqf[2] = __half22float2(sq2); sqf[3] = __half22float2(sq3);
    float2 xya = __half22float2(xy01);
    float2 xyb = __half22float2(xy23);
    float sxy[4] = {xya.x, xya.y, xyb.x, xyb.y};

    const float CF = 0.3f * 0.1f / (float)KNB;  // 0.002
    uint4 outp;
    unsigned int* op = (unsigned int*)&outp;
    float ore[4], oim[4];
#pragma unroll
    for (int qc = 0; qc < 4; qc++) {
        float vx = v[qc].x, vy = v[qc].y;
        float ir = vx * sqf[qc].x + vy * sxy[qc];
        float ii = vx * sxy[qc]   + vy * sqf[qc].y;
        float a2 = fmaxf(vx * vx + vy * vy, 1e-30f);
        float inv = rsqrtf(a2);
        float amp = a2 * inv;
        ore[qc] = 0.7f * amp * vx + CF * inv * ir;
        oim[qc] = 0.7f * amp * vy + CF * inv * ii;
        __half2 h = __floats2half2_rn(ore[qc], oim[qc]);
        op[qc] = *(unsigned int*)&h;
    }
    *(uint4*)(g_new + base) = outp;

    // fused emission: only lasing blocks; 1024 distinct 128B lines -> ~4 cyc/chain
    if (g_lasing[cell]) {
#pragma unroll
        for (int qc = 0; qc < 4; qc++) {
            atomicAdd(&g_em_re_s[(chbase + qc) * EM_STRIDE], ore[qc]);
            atomicAdd(&g_em_im_s[(chbase + qc) * EM_STRIDE], oim[qc]);
        }
    }
}

// ---------------- K5a: cavity update ----------------
__global__ void __launch_bounds__(512) k_cav_update(const float* __restrict__ cav_re,
                                                    const float* __restrict__ cav_im) {
    int t = threadIdx.x;
    int nl = g_nlasing;
    float inv = 1.f / fmaxf((float)nl, 1.f);
    float cr = cav_re[t], ci = cav_im[t];
    float er = g_em_re_s[t * EM_STRIDE];
    float ei = g_em_im_s[t * EM_STRIDE];
    float nr = (nl > 0) ? 0.8f * cr + 0.2f * (er * inv) : cr;
    float ni = (nl > 0) ? 0.8f * ci + 0.2f * (ei * inv) : ci;
    g_cavn_re[t] = nr;
    g_cavn_im[t] = ni;
    g_cav_phase[t] = atan2f(ci, cr);   // OLD cavity phase
}

// ---------------- K5b: decode GEMV ----------------
__global__ void __launch_bounds__(128) k_decode(const float* __restrict__ decW,
                                                const float* __restrict__ decb,
                                                float* __restrict__ out) {
    int d = blockIdx.x;
    int t = threadIdx.x;
    const float* w = decW + (size_t)d * (2 * H);
    float s = 0.f;
#pragma unroll
    for (int j = t; j < 2 * H; j += 128) {
        float v = (j < H) ? g_cavn_re[j] : g_cavn_im[j - H];
        s = fmaf(v, w[j], s);
    }
#pragma unroll
    for (int o = 16; o; o >>= 1) s += __shfl_xor_sync(0xFFFFFFFFu, s, o);
    __shared__ float red[4];
    if ((t & 31) == 0) red[t >> 5] = s;
    __syncthreads();
    if (t == 0) out[d] = red[0] + red[1] + red[2] + red[3] + decb[d];
}

// ---------------- K6: finalize + variance + fused tension ----------------
__global__ void __launch_bounds__(128) k_final(float* __restrict__ out, int out_size) {
    int cell = blockIdx.x;
    int t = threadIdx.x;
    int wid = t >> 5, lane = t & 31;
    __shared__ float wmax[4];
    __shared__ float ws[4], ws2[4];

    size_t base = (size_t)cell * H + (size_t)t * 4;
    uint4 p = *(const uint4*)(g_new + base);
    float2 c0 = __half22float2(*(const __half2*)&p.x);
    float2 c1 = __half22float2(*(const __half2*)&p.y);
    float2 c2 = __half22float2(*(const __half2*)&p.z);
    float2 c3 = __half22float2(*(const __half2*)&p.w);
    int las = g_lasing[cell];

    float amp[4];
    float re_[4] = {c0.x, c1.x, c2.x, c3.x};
    float im_[4] = {c0.y, c1.y, c2.y, c3.y};
    float mx = 0.f;
#pragma unroll
    for (int q = 0; q < 4; q++) {
        int h = t * 4 + q;
        float re = re_[q], im = im_[q];
        if (las) {
            float a = sqrtf(re * re + im * im);
            float ang = 0.3f * g_cav_phase[h] + 0.7f * atan2f(im, re);
            float sn, cs;
            __sincosf(ang, &sn, &cs);
            re = a * cs;
            im = a * sn;
        }
        re += 0.05f * g_cavn_re[h];
        im += 0.05f * g_cavn_im[h];
        amp[q] = sqrtf(re * re + im * im);
        mx = fmaxf(mx, amp[q]);
    }
#pragma unroll
    for (int o = 16; o; o >>= 1) mx = fmaxf(mx, __shfl_xor_sync(0xFFFFFFFFu, mx, o));
    if (lane == 0) wmax[wid] = mx;
    __syncthreads();
    float bmax = fmaxf(fmaxf(wmax[0], wmax[1]), fmaxf(wmax[2], wmax[3]));
    float inv = 1.f / (bmax + 1e-8f);

    float s = 0.f, s2 = 0.f;
#pragma unroll
    for (int q = 0; q < 4; q++) {
        float an = amp[q] * inv;
        s += an;
        s2 = fmaf(an, an, s2);
    }
#pragma unroll
    for (int o = 16; o; o >>= 1) {
        s  += __shfl_xor_sync(0xFFFFFFFFu, s, o);
        s2 += __shfl_xor_sync(0xFFFFFFFFu, s2, o);
    }
    if (lane == 0) { ws[wid] = s; ws2[wid] = s2; }
    __syncthreads();
    if (t == 0) {
        float bs  = ws[0] + ws[1] + ws[2] + ws[3];
        float bs2 = ws2[0] + ws2[1] + ws2[2] + ws2[3];
        atomicAdd(&g_sum,  (double)bs);
        atomicAdd(&g_sum2, (double)bs2);
        __threadfence();
        unsigned int done = atomicAdd(&g_done, 1u);
        if (done == gridDim.x - 1) {
            double S  = atomicAdd(&g_sum,  0.0);
            double S2 = atomicAdd(&g_sum2, 0.0);
            double M = (double)N_CELLS * (double)H;
            double mean = S / M;
            double var = S2 / M - mean * mean;
            out[out_size - 1] = (float)var;
        }
    }
}

// ---------------- launcher ----------------
extern "C" void kernel_launch(void* const* d_in, const int* in_sizes, int n_in,
                              void* d_out, int out_size) {
    const float* x       = (const float*)d_in[0];
    const float* pump_W  = (const float*)d_in[1];
    const float* pump_b  = (const float*)d_in[2];
    const float* dec_W   = (const float*)d_in[3];
    const float* dec_b   = (const float*)d_in[4];
    const float* cs_re   = (const float*)d_in[5];
    const float* cs_im   = (const float*)d_in[6];
    const float* excited = (const float*)d_in[7];
    const float* phase_v = (const float*)d_in[8];
    const float* cav_re  = (const float*)d_in[9];
    const float* cav_im  = (const float*)d_in[10];
    const int*   nbr     = (const int*)d_in[11];
    float* out = (float*)d_out;

    k_rot<<<(N_CELLS * H / 4) / 256, 256>>>((const float4*)cs_re,
                                            (const float4*)cs_im,
                                            (const float4*)phase_v);
    k_pump<<<N_CELLS / 8, 256>>>(x, pump_W, pump_b, excited);
    k_couple<<<N_CELLS, 128>>>(nbr);
    k_cav_update<<<1, 512>>>(cav_re, cav_im);
    k_decode<<<D, 128>>>(dec_W, dec_b, out);
    k_final<<<N_CELLS, 128>>>(out, out_size);
}

// round 15
// speedup vs baseline: 1.2471x; 1.0145x over previous
#include <cuda_runtime.h>
#include <cuda_fp16.h>
#include <math.h>
#include <stdint.h>

#define N_CELLS 16384
#define H 512
#define D 512
#define KNB 15
#define EM_STRIDE 32          // one fp32 accumulator per 128B line

#define PUMP_BLOCKS (N_CELLS / 8)             // 2048
#define ROT_BLOCKS  ((N_CELLS * H / 4) / 256) // 8192

// ---------------- scratch ----------------
__device__ __align__(16) __half2 g_v  [N_CELLS * H];   // v = sqrt(|s|)*unit(s)
__device__ __align__(16) __half2 g_new[N_CELLS * H];
__device__ int    g_lasing[N_CELLS];
__device__ int    g_nlasing;          // reset by k_final's last block (starts 0 in BSS)
__device__ float  g_em_re_s[H * EM_STRIDE];   // line-spread accumulators
__device__ float  g_em_im_s[H * EM_STRIDE];
__device__ float  g_cavn_re[H];
__device__ float  g_cavn_im[H];
__device__ float  g_cav_phase[H];
__device__ double g_sum, g_sum2;
__device__ unsigned int g_done;

// ---------------- K1: fused pump (blocks [0,2048)) + rotate (rest) -----------
__global__ void k_rotpump(const float4* __restrict__ cr,
                          const float4* __restrict__ ci,
                          const float4* __restrict__ pv,
                          const float*  __restrict__ x,
                          const float*  __restrict__ W,
                          const float*  __restrict__ b,
                          const float*  __restrict__ excited) {
    if (blockIdx.x < PUMP_BLOCKS) {
        // ---- pump role: 8 warps = 8 cells ----
        int warp = threadIdx.x >> 5;
        int lane = threadIdx.x & 31;
        int cell = blockIdx.x * 8 + warp;
        const float* w = W + (size_t)cell * D;
        float s = 0.f;
#pragma unroll
        for (int t = 0; t < D / 32; t++)
            s += x[lane + 32 * t] * w[lane + 32 * t];
#pragma unroll
        for (int o = 16; o; o >>= 1) s += __shfl_xor_sync(0xFFFFFFFFu, s, o);
        __shared__ int sflag[8];
        if (lane == 0) {
            float z = s + b[cell];
            float pump = 1.f / (1.f + expf(-z));
            float e = excited[cell] * 0.95f + pump * 0.05f;
            e = fminf(fmaxf(e, 0.f), 1.f);
            int las = (e > 0.5f) ? 1 : 0;
            g_lasing[cell] = las;
            sflag[warp] = las;
        }
        __syncthreads();
        if (threadIdx.x < 8) {
            unsigned m = __ballot_sync(0x000000FFu, sflag[threadIdx.x]);
            if (threadIdx.x == 0 && m) atomicAdd(&g_nlasing, __popc(m));
        }
        return;
    }

    // ---- rot role ----
    int rb = blockIdx.x - PUMP_BLOCKS;
    if (rb == 0) {
        float4 z4 = make_float4(0.f, 0.f, 0.f, 0.f);
        for (int j = threadIdx.x; j < H * EM_STRIDE / 4; j += blockDim.x) {
            ((float4*)g_em_re_s)[j] = z4;
            ((float4*)g_em_im_s)[j] = z4;
        }
        if (threadIdx.x == 0) { g_sum = 0.0; g_sum2 = 0.0; g_done = 0u; }
    }
    int i = rb * blockDim.x + threadIdx.x;   // over N*H/4
    float4 a4 = cr[i], b4 = ci[i], p4 = pv[i];
    float ax[4] = {a4.x, a4.y, a4.z, a4.w};
    float bx[4] = {b4.x, b4.y, b4.z, b4.w};
    float px[4] = {p4.x, p4.y, p4.z, p4.w};
    uint4 outp;
    unsigned int* op = (unsigned int*)&outp;
#pragma unroll
    for (int q = 0; q < 4; q++) {
        float ang = 0.1f * px[q];
        float a2 = ang * ang;
        float cs = 1.f - 0.5f * a2;
        float sn = ang * (1.f - a2 * (1.f / 6.f));
        float re = ax[q] * cs - bx[q] * sn;
        float im = ax[q] * sn + bx[q] * cs;
        float m2 = fmaxf(re * re + im * im, 1e-30f);
        float qm = rsqrtf(sqrtf(m2));               // |s|^(-1/2)
        __half2 h = __floats2half2_rn(re * qm, im * qm);
        op[q] = *(unsigned int*)&h;
    }
    *(uint4*)((unsigned int*)g_v + (size_t)i * 4) = outp;
}

// ---------------- K2: coupling (Gram) + fused line-spread emission ----------
__global__ void __launch_bounds__(128) k_couple(const int* __restrict__ nbr) {
    int cell = blockIdx.x;
    int t = threadIdx.x;
    __shared__ int snb[16];
    if (t < KNB) snb[t] = nbr[cell * KNB + t];
    __syncthreads();

    int chbase = t * 4;
    const __half2 z2 = __floats2half2_rn(0.f, 0.f);
    __half2 sq0 = z2, sq1 = z2, sq2 = z2, sq3 = z2;
    __half2 xy01 = z2, xy23 = z2;

#pragma unroll 3
    for (int j = 0; j < KNB; j++) {
        const uint4 np = *(const uint4*)(g_v + (size_t)snb[j] * H + chbase);
        __half2 n0 = *(const __half2*)&np.x;
        __half2 n1 = *(const __half2*)&np.y;
        __half2 n2 = *(const __half2*)&np.z;
        __half2 n3 = *(const __half2*)&np.w;
        sq0 = __hfma2(n0, n0, sq0);
        sq1 = __hfma2(n1, n1, sq1);
        sq2 = __hfma2(n2, n2, sq2);
        sq3 = __hfma2(n3, n3, sq3);
        unsigned int p, q;
        p = __byte_perm(np.x, np.y, 0x5410);
        q = __byte_perm(np.x, np.y, 0x7632);
        xy01 = __hfma2(*(__half2*)&p, *(__half2*)&q, xy01);
        p = __byte_perm(np.z, np.w, 0x5410);
        q = __byte_perm(np.z, np.w, 0x7632);
        xy23 = __hfma2(*(__half2*)&p, *(__half2*)&q, xy23);
    }

    size_t base = (size_t)cell * H + chbase;
    uint4 vp = *(const uint4*)(g_v + base);
    float2 v[4];
    v[0] = __half22float2(*(const __half2*)&vp.x);
    v[1] = __half22float2(*(const __half2*)&vp.y);
    v[2] = __half22float2(*(const __half2*)&vp.z);
    v[3] = __half22float2(*(const __half2*)&vp.w);

    float2 sqf[4];
    sqf[0] = __half22float2(sq0); sqf[1] = __half22float2(sq1);
    sqf[2] = __half22float2(sq2); sqf[3] = __half22float2(sq3);
    float2 xya = __half22float2(xy01);
    float2 xyb = __half22float2(xy23);
    float sxy[4] = {xya.x, xya.y, xyb.x, xyb.y};

    const float CF = 0.3f * 0.1f / (float)KNB;  // 0.002
    uint4 outp;
    unsigned int* op = (unsigned int*)&outp;
    float ore[4], oim[4];
#pragma unroll
    for (int qc = 0; qc < 4; qc++) {
        float vx = v[qc].x, vy = v[qc].y;
        float ir = vx * sqf[qc].x + vy * sxy[qc];
        float ii = vx * sxy[qc]   + vy * sqf[qc].y;
        float a2 = fmaxf(vx * vx + vy * vy, 1e-30f);
        float inv = rsqrtf(a2);
        float amp = a2 * inv;
        ore[qc] = 0.7f * amp * vx + CF * inv * ir;
        oim[qc] = 0.7f * amp * vy + CF * inv * ii;
        __half2 h = __floats2half2_rn(ore[qc], oim[qc]);
        op[qc] = *(unsigned int*)&h;
    }
    *(uint4*)(g_new + base) = outp;

    if (g_lasing[cell]) {
#pragma unroll
        for (int qc = 0; qc < 4; qc++) {
            atomicAdd(&g_em_re_s[(chbase + qc) * EM_STRIDE], ore[qc]);
            atomicAdd(&g_em_im_s[(chbase + qc) * EM_STRIDE], oim[qc]);
        }
    }
}

// ---------------- K3: fused cavity update + decode GEMV ----------------
// grid = 512 blocks x 128 threads; each block rebuilds sv[1024] (cheap, L2-hot);
// block 0 additionally publishes cavn + old-cavity phase for k_final.
__global__ void __launch_bounds__(128) k_cavdec(const float* __restrict__ cav_re,
                                                const float* __restrict__ cav_im,
                                                const float* __restrict__ decW,
                                                const float* __restrict__ decb,
                                                float* __restrict__ out) {
    __shared__ float sv[2 * H];
    int t = threadIdx.x;
    int nl = g_nlasing;
    float inv = 1.f / fmaxf((float)nl, 1.f);
#pragma unroll
    for (int q = 0; q < 4; q++) {
        int j = t * 4 + q;     // 0..511
        float crj = cav_re[j], cij = cav_im[j];
        float er = g_em_re_s[j * EM_STRIDE];
        float ei = g_em_im_s[j * EM_STRIDE];
        float nr = (nl > 0) ? 0.8f * crj + 0.2f * (er * inv) : crj;
        float ni = (nl > 0) ? 0.8f * cij + 0.2f * (ei * inv) : cij;
        sv[j] = nr;
        sv[H + j] = ni;
        if (blockIdx.x == 0) {
            g_cavn_re[j] = nr;
            g_cavn_im[j] = ni;
            g_cav_phase[j] = atan2f(cij, crj);   // OLD cavity phase
        }
    }
    __syncthreads();

    int d = blockIdx.x;
    const float* w = decW + (size_t)d * (2 * H);
    float s = 0.f;
#pragma unroll
    for (int j = t; j < 2 * H; j += 128)
        s = fmaf(sv[j], w[j], s);
#pragma unroll
    for (int o = 16; o; o >>= 1) s += __shfl_xor_sync(0xFFFFFFFFu, s, o);
    __shared__ float red[4];
    if ((t & 31) == 0) red[t >> 5] = s;
    __syncthreads();
    if (t == 0) out[d] = red[0] + red[1] + red[2] + red[3] + decb[d];
}

// ---------------- K4: finalize + variance + fused tension ----------------
__global__ void __launch_bounds__(128) k_final(float* __restrict__ out, int out_size) {
    int cell = blockIdx.x;
    int t = threadIdx.x;
    int wid = t >> 5, lane = t & 31;
    __shared__ float wmax[4];
    __shared__ float ws[4], ws2[4];

    size_t base = (size_t)cell * H + (size_t)t * 4;
    uint4 p = *(const uint4*)(g_new + base);
    float2 c0 = __half22float2(*(const __half2*)&p.x);
    float2 c1 = __half22float2(*(const __half2*)&p.y);
    float2 c2 = __half22float2(*(const __half2*)&p.z);
    float2 c3 = __half22float2(*(const __half2*)&p.w);
    int las = g_lasing[cell];

    float amp[4];
    float re_[4] = {c0.x, c1.x, c2.x, c3.x};
    float im_[4] = {c0.y, c1.y, c2.y, c3.y};
    float mx = 0.f;
#pragma unroll
    for (int q = 0; q < 4; q++) {
        int h = t * 4 + q;
        float re = re_[q], im = im_[q];
        if (las) {
            float a = sqrtf(re * re + im * im);
            float ang = 0.3f * g_cav_phase[h] + 0.7f * atan2f(im, re);
            float sn, cs;
            __sincosf(ang, &sn, &cs);
            re = a * cs;
            im = a * sn;
        }
        re += 0.05f * g_cavn_re[h];
        im += 0.05f * g_cavn_im[h];
        amp[q] = sqrtf(re * re + im * im);
        mx = fmaxf(mx, amp[q]);
    }
#pragma unroll
    for (int o = 16; o; o >>= 1) mx = fmaxf(mx, __shfl_xor_sync(0xFFFFFFFFu, mx, o));
    if (lane == 0) wmax[wid] = mx;
    __syncthreads();
    float bmax = fmaxf(fmaxf(wmax[0], wmax[1]), fmaxf(wmax[2], wmax[3]));
    float inv = 1.f / (bmax + 1e-8f);

    float s = 0.f, s2 = 0.f;
#pragma unroll
    for (int q = 0; q < 4; q++) {
        float an = amp[q] * inv;
        s += an;
        s2 = fmaf(an, an, s2);
    }
#pragma unroll
    for (int o = 16; o; o >>= 1) {
        s  += __shfl_xor_sync(0xFFFFFFFFu, s, o);
        s2 += __shfl_xor_sync(0xFFFFFFFFu, s2, o);
    }
    if (lane == 0) { ws[wid] = s; ws2[wid] = s2; }
    __syncthreads();
    if (t == 0) {
        float bs  = ws[0] + ws[1] + ws[2] + ws[3];
        float bs2 = ws2[0] + ws2[1] + ws2[2] + ws2[3];
        atomicAdd(&g_sum,  (double)bs);
        atomicAdd(&g_sum2, (double)bs2);
        __threadfence();
        unsigned int done = atomicAdd(&g_done, 1u);
        if (done == gridDim.x - 1) {
            double S  = atomicAdd(&g_sum,  0.0);
            double S2 = atomicAdd(&g_sum2, 0.0);
            double M = (double)N_CELLS * (double)H;
            double mean = S / M;
            double var = S2 / M - mean * mean;
            out[out_size - 1] = (float)var;
            g_nlasing = 0;     // reset for next graph replay (BSS starts at 0)
        }
    }
}

// ---------------- launcher ----------------
extern "C" void kernel_launch(void* const* d_in, const int* in_sizes, int n_in,
                              void* d_out, int out_size) {
    const float* x       = (const float*)d_in[0];
    const float* pump_W  = (const float*)d_in[1];
    const float* pump_b  = (const float*)d_in[2];
    const float* dec_W   = (const float*)d_in[3];
    const float* dec_b   = (const float*)d_in[4];
    const float* cs_re   = (const float*)d_in[5];
    const float* cs_im   = (const float*)d_in[6];
    const float* excited = (const float*)d_in[7];
    const float* phase_v = (const float*)d_in[8];
    const float* cav_re  = (const float*)d_in[9];
    const float* cav_im  = (const float*)d_in[10];
    const int*   nbr     = (const int*)d_in[11];
    float* out = (float*)d_out;

    k_rotpump<<<PUMP_BLOCKS + ROT_BLOCKS, 256>>>((const float4*)cs_re,
                                                 (const float4*)cs_im,
                                                 (const float4*)phase_v,
                                                 x, pump_W, pump_b, excited);
    k_couple<<<N_CELLS, 128>>>(nbr);
    k_cavdec<<<D, 128>>>(cav_re, cav_im, dec_W, dec_b, out);
    k_final<<<N_CELLS, 128>>>(out, out_size);
}

// round 17
// speedup vs baseline: 1.4326x; 1.1487x over previous
#include <cuda_runtime.h>
#include <cuda_fp16.h>
#include <math.h>
#include <stdint.h>

#define N_CELLS 16384
#define H 512
#define D 512
#define KNB 15
#define EM_STRIDE 32          // one fp32 accumulator per 128B line
#define VSLOTS 64             // variance accumulator slots (1 per 128B line)

#define PUMP_BLOCKS (N_CELLS / 8)             // 2048
#define ROT_BLOCKS  ((N_CELLS * H / 4) / 256) // 8192

// ---------------- scratch ----------------
__device__ __align__(16) __half2 g_v  [N_CELLS * H];   // v = sqrt(|s|)*unit(s)
__device__ __align__(16) __half2 g_new[N_CELLS * H];
__device__ int    g_lasing[N_CELLS];
__device__ int    g_nlasing;          // reset by k_final's last block (starts 0 in BSS)
__device__ float  g_em_re_s[H * EM_STRIDE];   // line-spread emission accumulators
__device__ float  g_em_im_s[H * EM_STRIDE];
__device__ float  g_cavn_re[H];
__device__ float  g_cavn_im[H];
__device__ float  g_cav_phase[H];
__device__ double g_sum_s [VSLOTS * 16];      // line-spread variance slots (stride 16 dbl = 128B)
__device__ double g_sum2_s[VSLOTS * 16];
__device__ unsigned int g_done;

// ---------------- K1: fused pump (blocks [0,2048)) + rotate (rest) -----------
__global__ void k_rotpump(const float4* __restrict__ cr,
                          const float4* __restrict__ ci,
                          const float4* __restrict__ pv,
                          const float*  __restrict__ x,
                          const float*  __restrict__ W,
                          const float*  __restrict__ b,
                          const float*  __restrict__ excited) {
    if (blockIdx.x < PUMP_BLOCKS) {
        int warp = threadIdx.x >> 5;
        int lane = threadIdx.x & 31;
        int cell = blockIdx.x * 8 + warp;
        const float* w = W + (size_t)cell * D;
        float s = 0.f;
#pragma unroll
        for (int t = 0; t < D / 32; t++)
            s += x[lane + 32 * t] * w[lane + 32 * t];
#pragma unroll
        for (int o = 16; o; o >>= 1) s += __shfl_xor_sync(0xFFFFFFFFu, s, o);
        __shared__ int sflag[8];
        if (lane == 0) {
            float z = s + b[cell];
            float pump = 1.f / (1.f + expf(-z));
            float e = excited[cell] * 0.95f + pump * 0.05f;
            e = fminf(fmaxf(e, 0.f), 1.f);
            int las = (e > 0.5f) ? 1 : 0;
            g_lasing[cell] = las;
            sflag[warp] = las;
        }
        __syncthreads();
        if (threadIdx.x < 8) {
            unsigned m = __ballot_sync(0x000000FFu, sflag[threadIdx.x]);
            if (threadIdx.x == 0 && m) atomicAdd(&g_nlasing, __popc(m));
        }
        return;
    }

    int rb = blockIdx.x - PUMP_BLOCKS;
    if (rb == 0) {
        float4 z4 = make_float4(0.f, 0.f, 0.f, 0.f);
        for (int j = threadIdx.x; j < H * EM_STRIDE / 4; j += blockDim.x) {
            ((float4*)g_em_re_s)[j] = z4;
            ((float4*)g_em_im_s)[j] = z4;
        }
        for (int j = threadIdx.x; j < VSLOTS * 16; j += blockDim.x) {
            g_sum_s[j] = 0.0; g_sum2_s[j] = 0.0;
        }
        if (threadIdx.x == 0) g_done = 0u;
    }
    int i = rb * blockDim.x + threadIdx.x;   // over N*H/4
    float4 a4 = cr[i], b4 = ci[i], p4 = pv[i];
    float ax[4] = {a4.x, a4.y, a4.z, a4.w};
    float bx[4] = {b4.x, b4.y, b4.z, b4.w};
    float px[4] = {p4.x, p4.y, p4.z, p4.w};
    uint4 outp;
    unsigned int* op = (unsigned int*)&outp;
#pragma unroll
    for (int q = 0; q < 4; q++) {
        float ang = 0.1f * px[q];
        float a2 = ang * ang;
        float cs = 1.f - 0.5f * a2;
        float sn = ang * (1.f - a2 * (1.f / 6.f));
        float re = ax[q] * cs - bx[q] * sn;
        float im = ax[q] * sn + bx[q] * cs;
        float m2 = fmaxf(re * re + im * im, 1e-30f);
        float qm = rsqrtf(sqrtf(m2));               // |s|^(-1/2)
        __half2 h = __floats2half2_rn(re * qm, im * qm);
        op[q] = *(unsigned int*)&h;
    }
    *(uint4*)((unsigned int*)g_v + (size_t)i * 4) = outp;
}

// ---------------- K2: coupling (Gram) + fused line-spread emission ----------
__global__ void __launch_bounds__(128) k_couple(const int* __restrict__ nbr) {
    int cell = blockIdx.x;
    int t = threadIdx.x;
    __shared__ int snb[16];
    if (t < KNB) snb[t] = nbr[cell * KNB + t];
    __syncthreads();

    int chbase = t * 4;
    const __half2 z2 = __floats2half2_rn(0.f, 0.f);
    __half2 sq0 = z2, sq1 = z2, sq2 = z2, sq3 = z2;
    __half2 xy01 = z2, xy23 = z2;

#pragma unroll 3
    for (int j = 0; j < KNB; j++) {
        const uint4 np = *(const uint4*)(g_v + (size_t)snb[j] * H + chbase);
        __half2 n0 = *(const __half2*)&np.x;
        __half2 n1 = *(const __half2*)&np.y;
        __half2 n2 = *(const __half2*)&np.z;
        __half2 n3 = *(const __half2*)&np.w;
        sq0 = __hfma2(n0, n0, sq0);
        sq1 = __hfma2(n1, n1, sq1);
        sq2 = __hfma2(n2, n2, sq2);
        sq3 = __hfma2(n3, n3, sq3);
        unsigned int p, q;
        p = __byte_perm(np.x, np.y, 0x5410);
        q = __byte_perm(np.x, np.y, 0x7632);
        xy01 = __hfma2(*(__half2*)&p, *(__half2*)&q, xy01);
        p = __byte_perm(np.z, np.w, 0x5410);
        q = __byte_perm(np.z, np.w, 0x7632);
        xy23 = __hfma2(*(__half2*)&p, *(__half2*)&q, xy23);
    }

    size_t base = (size_t)cell * H + chbase;
    uint4 vp = *(const uint4*)(g_v + base);
    float2 v[4];
    v[0] = __half22float2(*(const __half2*)&vp.x);
    v[1] = __half22float2(*(const __half2*)&vp.y);
    v[2] = __half22float2(*(const __half2*)&vp.z);
    v[3] = __half22float2(*(const __half2*)&vp.w);

    float2 sqf[4];
    sqf[0] = __half22float2(sq0); sqf[1] = __half22float2(sq1);
    sqf[2] = __half22float2(sq2); sqf[3] = __half22float2(sq3);
    float2 xya = __half22float2(xy01);
    float2 xyb = __half22float2(xy23);
    float sxy[4] = {xya.x, xya.y, xyb.x, xyb.y};

    const float CF = 0.3f * 0.1f / (float)KNB;  // 0.002
    uint4 outp;
    unsigned int* op = (unsigned int*)&outp;
    float ore[4], oim[4];
#pragma unroll
    for (int qc = 0; qc < 4; qc++) {
        float vx = v[qc].x, vy = v[qc].y;
        float ir = vx * sqf[qc].x + vy * sxy[qc];
        float ii = vx * sxy[qc]   + vy * sqf[qc].y;
        float a2 = fmaxf(vx * vx + vy * vy, 1e-30f);
        float inv = rsqrtf(a2);
        float amp = a2 * inv;
        ore[qc] = 0.7f * amp * vx + CF * inv * ir;
        oim[qc] = 0.7f * amp * vy + CF * inv * ii;
        __half2 h = __floats2half2_rn(ore[qc], oim[qc]);
        op[qc] = *(unsigned int*)&h;
    }
    *(uint4*)(g_new + base) = outp;

    if (g_lasing[cell]) {
#pragma unroll
        for (int qc = 0; qc < 4; qc++) {
            atomicAdd(&g_em_re_s[(chbase + qc) * EM_STRIDE], ore[qc]);
            atomicAdd(&g_em_im_s[(chbase + qc) * EM_STRIDE], oim[qc]);
        }
    }
}

// ---------------- K3: fused cavity update + decode GEMV ----------------
__global__ void __launch_bounds__(128) k_cavdec(const float* __restrict__ cav_re,
                                                const float* __restrict__ cav_im,
                                                const float* __restrict__ decW,
                                                const float* __restrict__ decb,
                                                float* __restrict__ out) {
    __shared__ float sv[2 * H];
    int t = threadIdx.x;
    int nl = g_nlasing;
    float inv = 1.f / fmaxf((float)nl, 1.f);
#pragma unroll
    for (int q = 0; q < 4; q++) {
        int j = t * 4 + q;     // 0..511
        float crj = cav_re[j], cij = cav_im[j];
        float er = g_em_re_s[j * EM_STRIDE];
        float ei = g_em_im_s[j * EM_STRIDE];
        float nr = (nl > 0) ? 0.8f * crj + 0.2f * (er * inv) : crj;
        float ni = (nl > 0) ? 0.8f * cij + 0.2f * (ei * inv) : cij;
        sv[j] = nr;
        sv[H + j] = ni;
        if (blockIdx.x == 0) {
            g_cavn_re[j] = nr;
            g_cavn_im[j] = ni;
            g_cav_phase[j] = atan2f(cij, crj);   // OLD cavity phase
        }
    }
    __syncthreads();

    int d = blockIdx.x;
    const float* w = decW + (size_t)d * (2 * H);
    float s = 0.f;
#pragma unroll
    for (int j = t; j < 2 * H; j += 128)
        s = fmaf(sv[j], w[j], s);
#pragma unroll
    for (int o = 16; o; o >>= 1) s += __shfl_xor_sync(0xFFFFFFFFu, s, o);
    __shared__ float red[4];
    if ((t & 31) == 0) red[t >> 5] = s;
    __syncthreads();
    if (t == 0) out[d] = red[0] + red[1] + red[2] + red[3] + decb[d];
}

// ---------------- K4: finalize, warp-per-cell, line-spread accumulators ------
__global__ void __launch_bounds__(128) k_final(float* __restrict__ out, int out_size) {
    int t = threadIdx.x;
    int w = t >> 5, lane = t & 31;
    int cell = blockIdx.x * 4 + w;
    int las = g_lasing[cell];
    const __half2* row = g_new + (size_t)cell * H;

    // 4 independent coalesced loads: lane covers channels k*128 + lane*4 .. +3
    uint4 p[4];
#pragma unroll
    for (int k = 0; k < 4; k++)
        p[k] = *(const uint4*)(row + k * 128 + lane * 4);

    float amp[16];
    float mx = 0.f;
#pragma unroll
    for (int k = 0; k < 4; k++) {
        unsigned int* pp = (unsigned int*)&p[k];
#pragma unroll
        for (int q = 0; q < 4; q++) {
            int h = k * 128 + lane * 4 + q;
            float2 c = __half22float2(*(const __half2*)&pp[q]);
            float re = c.x, im = c.y;
            if (las) {
                float a = sqrtf(re * re + im * im);
                float ang = 0.3f * g_cav_phase[h] + 0.7f * atan2f(im, re);
                float sn, cs;
                __sincosf(ang, &sn, &cs);
                re = a * cs;
                im = a * sn;
            }
            re += 0.05f * g_cavn_re[h];
            im += 0.05f * g_cavn_im[h];
            float a2 = sqrtf(re * re + im * im);
            amp[k * 4 + q] = a2;
            mx = fmaxf(mx, a2);
        }
    }
    // warp-wide max (whole cell lives in this warp)
#pragma unroll
    for (int o = 16; o; o >>= 1) mx = fmaxf(mx, __shfl_xor_sync(0xFFFFFFFFu, mx, o));
    float inv = 1.f / (mx + 1e-8f);

    float s = 0.f, s2 = 0.f;
#pragma unroll
    for (int q = 0; q < 16; q++) {
        float an = amp[q] * inv;
        s += an;
        s2 = fmaf(an, an, s2);
    }
#pragma unroll
    for (int o = 16; o; o >>= 1) {
        s  += __shfl_xor_sync(0xFFFFFFFFu, s, o);
        s2 += __shfl_xor_sync(0xFFFFFFFFu, s2, o);
    }

    __shared__ double bs[4], bs2[4];
    __shared__ int is_last;
    if (lane == 0) { bs[w] = (double)s; bs2[w] = (double)s2; }
    __syncthreads();
    if (t == 0) {
        int slot = (blockIdx.x & (VSLOTS - 1)) * 16;
        atomicAdd(&g_sum_s[slot],  bs[0] + bs[1] + bs[2] + bs[3]);
        atomicAdd(&g_sum2_s[slot], bs2[0] + bs2[1] + bs2[2] + bs2[3]);
        __threadfence();
        is_last = (atomicAdd(&g_done, 1u) == gridDim.x - 1) ? 1 : 0;
    }
    __syncthreads();
    if (is_last && t < 32) {
        double S = 0.0, S2 = 0.0;
#pragma unroll
        for (int k = 0; k < VSLOTS / 32; k++) {
            S  += g_sum_s [(t + 32 * k) * 16];
            S2 += g_sum2_s[(t + 32 * k) * 16];
        }
#pragma unroll
        for (int o = 16; o; o >>= 1) {
            S  += __shfl_xor_sync(0xFFFFFFFFu, S, o);
            S2 += __shfl_xor_sync(0xFFFFFFFFu, S2, o);
        }
        if (t == 0) {
            double M = (double)N_CELLS * (double)H;
            double mean = S / M;
            double var = S2 / M - mean * mean;
            out[out_size - 1] = (float)var;
            g_nlasing = 0;     // reset for next graph replay (BSS starts at 0)
        }
    }
}

// ---------------- launcher ----------------
extern "C" void kernel_launch(void* const* d_in, const int* in_sizes, int n_in,
                              void* d_out, int out_size) {
    const float* x       = (const float*)d_in[0];
    const float* pump_W  = (const float*)d_in[1];
    const float* pump_b  = (const float*)d_in[2];
    const float* dec_W   = (const float*)d_in[3];
    const float* dec_b   = (const float*)d_in[4];
    const float* cs_re   = (const float*)d_in[5];
    const float* cs_im   = (const float*)d_in[6];
    const float* excited = (const float*)d_in[7];
    const float* phase_v = (const float*)d_in[8];
    const float* cav_re  = (const float*)d_in[9];
    const float* cav_im  = (const float*)d_in[10];
    const int*   nbr     = (const int*)d_in[11];
    float* out = (float*)d_out;

    k_rotpump<<<PUMP_BLOCKS + ROT_BLOCKS, 256>>>((const float4*)cs_re,
                                                 (const float4*)cs_im,
                                                 (const float4*)phase_v,
                                                 x, pump_W, pump_b, excited);
    k_couple<<<N_CELLS, 128>>>(nbr);
    k_cavdec<<<D, 128>>>(cav_re, cav_im, dec_W, dec_b, out);
    k_final<<<N_CELLS / 4, 128>>>(out, out_size);
}